// round 11
// baseline (speedup 1.0000x reference)
#include <cuda_runtime.h>
#include <cstdint>

// Focal CTC loss — split bidirectional scan (1 CTA per sample+direction) with
// a permuted gather ring and fused focal-weight accumulation.
// grid = 2B = 128 CTAs (every CTA its own SM), block = 160 (5 warps).
//   dir = bid&1, b = bid>>1. Warps 0-3: compute pair j=tid (states 2j, 2j+1),
//   2 timesteps per __syncthreads (R9/R10 proven math). Warp 4: gather ring —
//   cp.async 4B per target channel builds permuted rows ring[slot][4+j] =
//   lp[t][b][ch_j] (+ blank in ringBl), so compute-side emission LDS is
//   conflict-free AND sum_t exp(lp[t,b,ch_j]) is accumulated for free by the
//   compute threads (no separate 64MB reduce pass at all).
//   fwd covers rows [0,Tm], bwd rows [Tm+1,len-1]; second CTA to finish a
//   sample combines ll = LSE_s(alpha_Tm + beta_Tm) and the focal weights.
// Final scalar factorizes: mean(outer(w,loss)) = mean(loss)*mean(w).

#define CFIX  256
#define DEPTH 8
#define RSTR  136               // ring row stride (4 front pads + 128 + 4 end)
#define NEG2  (-1e30f)
#define LOG2E 1.4426950408889634f
#define LN2   0.6931471805599453f

__device__ float    g_mid[64][2][128][2];   // alpha/beta at the meeting point
__device__ float    g_tps[64][2][128];      // partial sum_t exp per target pos
__device__ unsigned g_done[64];             // per-sample arrival counter
__device__ float    g_loss[64];
__device__ float    g_wsum[64];
__device__ unsigned g_ctr = 0;

__device__ __forceinline__ float ex2f(float x){ float y; asm("ex2.approx.ftz.f32 %0,%1;":"=f"(y):"f"(x)); return y; }
__device__ __forceinline__ float lg2f(float x){ float y; asm("lg2.approx.ftz.f32 %0,%1;":"=f"(y):"f"(x)); return y; }

// raw-emission forms (fwd): e in natural log, folded via fma
__device__ __forceinline__ float lse2p(float a, float b, float e) {
    float hi = fmaxf(a, b), lo = fminf(a, b);
    return fmaf(e, LOG2E, hi + lg2f(1.0f + ex2f(lo - hi)));
}
__device__ __forceinline__ float lse3p(float a, float b, float c, float e) {
    float hi = fmaxf(a, b), lo = fminf(a, b);
    float m  = fmaxf(hi, c), o1 = fminf(hi, c);
    return fmaf(e, LOG2E, m + lg2f(1.0f + ex2f(o1 - m) + ex2f(lo - m)));
}
// pre-added forms (bwd)
__device__ __forceinline__ float lse2(float a, float b) {
    float hi = fmaxf(a, b), lo = fminf(a, b);
    return hi + lg2f(1.0f + ex2f(lo - hi));
}
__device__ __forceinline__ float lse3(float a, float b, float c) {
    float hi = fmaxf(a, b), lo = fminf(a, b);
    float m  = fmaxf(hi, c), o1 = fminf(hi, c);
    return m + lg2f(1.0f + ex2f(o1 - m) + ex2f(lo - m));
}

__device__ __forceinline__ void finalize(float* out, int B, int L)
{
    __threadfence();
    unsigned v = atomicAdd(&g_ctr, 1u);
    if (v == (unsigned)(B - 1)) {
        g_ctr = 0;
        __threadfence();
        float ls = 0.0f, ws = 0.0f;
        for (int i = 0; i < B; i++) {
            ls += __ldcg(&g_loss[i]);
            ws += __ldcg(&g_wsum[i]);
        }
        out[0] = (ls / (float)B) * (ws / ((float)B * (float)L));
    }
}

__global__ __launch_bounds__(160, 1)
void focal_ctc_kernel(const float* __restrict__ lp,      // (T,B,C)
                      const int*   __restrict__ targets, // (B*L)
                      const int*   __restrict__ in_len,  // (B)
                      const int*   __restrict__ tg_len,  // (B)
                      float*       __restrict__ out,
                      int T, int B, int L)
{
    __shared__ float  ring[DEPTH][RSTR];  // permuted emission rows
    __shared__ float  ringBl[DEPTH];      // blank channel per row
    __shared__ float2 ab[2][132];         // alpha/beta exchange (fwd pads 0-1 front, bwd 128-131 end)
    __shared__ float  redm[4], reds[4], redww[4];
    __shared__ unsigned sflag;

    const int tid = threadIdx.x, w = tid >> 5, lane = tid & 31;
    const int bid = blockIdx.x;
    const int dir = bid & 1, b = bid >> 1;
    const int len = in_len[b], tl = tg_len[b];
    const int bL  = b * L;
    const int Tm  = len >> 1;
    const int nB  = len - 1 - Tm;
    const size_t tstr = (size_t)B * CFIX;
    const float* rowb = lp + (size_t)b * CFIX;

    // ---- shared init ----
    if (tid < 64) {                     // ring row pads (idx 0..3, 132..135), all slots
        int sl = tid >> 3, p = tid & 7;
        ring[sl][p < 4 ? p : 128 + p] = NEG2;
    }
    if (tid < 2)  { ab[0][tid] = make_float2(NEG2, NEG2); ab[1][tid] = make_float2(NEG2, NEG2); }
    if (tid >= 128 && tid < 132) {
        ab[0][tid] = make_float2(NEG2, NEG2); ab[1][tid] = make_float2(NEG2, NEG2);
    }

    // ---- gather warp state ----
    int chn0 = 0, chn1 = 0, chn2 = 0, chn3 = 0;
    uint32_t ringA = 0, ringBlA = 0;
    if (w == 4) {
        int j0 = lane, j1 = lane + 32, j2 = lane + 64, j3 = lane + 96;
        chn0 = (j0 < L) ? targets[bL + j0] : 0;
        chn1 = (j1 < L) ? targets[bL + j1] : 0;
        chn2 = (j2 < L) ? targets[bL + j2] : 0;
        chn3 = (j3 < L) ? targets[bL + j3] : 0;
        ringA   = (uint32_t)__cvta_generic_to_shared(&ring[0][0]);
        ringBlA = (uint32_t)__cvta_generic_to_shared(&ringBl[0]);
    }

    #define GATHER_ROW(r)                                                        \
    {                                                                            \
        const float* src = rowb + (size_t)(r) * tstr;                            \
        uint32_t d = ringA + (uint32_t)((r) & 7) * (RSTR * 4) + 16 + lane * 4;   \
        asm volatile("cp.async.ca.shared.global [%0], [%1], 4;" :: "r"(d),        "l"(src + chn0) : "memory"); \
        asm volatile("cp.async.ca.shared.global [%0], [%1], 4;" :: "r"(d + 128),  "l"(src + chn1) : "memory"); \
        asm volatile("cp.async.ca.shared.global [%0], [%1], 4;" :: "r"(d + 256),  "l"(src + chn2) : "memory"); \
        asm volatile("cp.async.ca.shared.global [%0], [%1], 4;" :: "r"(d + 384),  "l"(src + chn3) : "memory"); \
        if (lane == 0)                                                           \
            asm volatile("cp.async.ca.shared.global [%0], [%1], 4;" :: "r"(ringBlA + (uint32_t)((r) & 7) * 4), "l"(src) : "memory"); \
    }

    // ---- prologue: 7 rows in flight, 3 oldest complete ----
    if (w == 4) {
        #pragma unroll
        for (int i = 0; i < DEPTH - 1; i++) {
            int r = dir ? (len - 1 - i) : i;
            bool ok = dir ? (r >= 0 && i < nB + 1) : (r <= Tm);
            if (ok) GATHER_ROW(r)
            asm volatile("cp.async.commit_group;" ::: "memory");
        }
        asm volatile("cp.async.wait_group 4;" ::: "memory");
    }
    __syncthreads();

    // ---- compute-warp static state ----
    const int j = tid;                  // pair index (valid for w<4)
    bool hasU = false, hasV = false;
    bool al = false, hasVp = false, alp = false;       // fwd
    bool al1 = false, al2 = false;                     // bwd
    if (w < 4) {
        hasU = (j <= L); hasV = (j <= L - 1);
        if (dir == 0) {
            if (hasV && j >= 1) al = (targets[bL + j] != targets[bL + j - 1]);
            hasVp = (j >= 1) && (j - 1 <= L - 1);
            if (hasVp && j >= 2) alp = (targets[bL + j - 1] != targets[bL + j - 2]);
        } else {
            if (j + 1 <= L - 1) al1 = (targets[bL + j + 1] != targets[bL + j]);
            if (j + 2 <= L - 1) al2 = (targets[bL + j + 2] != targets[bL + j + 1]);
        }
    }

    float aU = NEG2, aV = NEG2, acc = 0.0f;

    if (dir == 0) {
        // ================= FORWARD =================
        if (w < 4) {
            if (j == 0) { aU = ringBl[0] * LOG2E; aV = ring[0][4] * LOG2E; }
            acc = ex2f(ring[0][4 + j] * LOG2E);
            ab[0][2 + j] = make_float2(aU, aV);
        }
        int rb = 0, t = 1;
        for (; t + 1 <= Tm; t += 2) {
            __syncthreads();
            if (w == 4) {
                #pragma unroll
                for (int k = 0; k < 2; k++) {
                    int r = t + 6 + k;
                    if (r <= Tm) GATHER_ROW(r)
                    asm volatile("cp.async.commit_group;" ::: "memory");
                }
                asm volatile("cp.async.wait_group 4;" ::: "memory");
            } else if (w < 4) {
                const int rt = t & 7, rn = (t + 1) & 7;
                float2 pv1 = ab[rb][1 + j];
                float  pv2 = ab[rb][j].y;
                float eB0 = ringBl[rt], eB1 = ringBl[rn];
                float eV0 = ring[rt][4 + j], eVp = ring[rt][3 + j], eV1 = ring[rn][4 + j];
                acc += ex2f(eV0 * LOG2E) + ex2f(eV1 * LOG2E);
                float aVm1 = pv1.y;
                float nU = lse2p(aU, aVm1, eB0);
                float nV = lse3p(aV, aU, al ? aVm1 : NEG2, eV0);
                nU = hasU ? nU : NEG2;  nV = hasV ? nV : NEG2;
                float nVp = lse3p(pv1.y, pv1.x, alp ? pv2 : NEG2, eVp);
                nVp = hasVp ? nVp : NEG2;
                float nU2 = lse2p(nU, nVp, eB1);
                float nV2 = lse3p(nV, nU, al ? nVp : NEG2, eV1);
                aU = hasU ? nU2 : NEG2;  aV = hasV ? nV2 : NEG2;
                ab[rb ^ 1][2 + j] = make_float2(aU, aV);
            }
            rb ^= 1;
        }
        if (t <= Tm) {                   // leftover single step
            __syncthreads();
            if (w < 4) {
                const int rt = t & 7;
                float aVm1 = ab[rb][1 + j].y;
                float eV0 = ring[rt][4 + j];
                acc += ex2f(eV0 * LOG2E);
                float nU = lse2p(aU, aVm1, ringBl[rt]);
                float nV = lse3p(aV, aU, al ? aVm1 : NEG2, eV0);
                aU = hasU ? nU : NEG2;  aV = hasV ? nV : NEG2;
            }
        }
    } else {
        // ================= BACKWARD =================
        if (w < 4) {
            aU = (j == tl)     ? 0.0f : NEG2;
            aV = (j == tl - 1) ? 0.0f : NEG2;
            ab[0][j] = make_float2(aU, aV);
        }
        int rb = 0, k = 0;
        for (; k + 1 < nB; k += 2) {
            __syncthreads();
            if (w == 4) {
                #pragma unroll
                for (int q = 0; q < 2; q++) {
                    int r = len - 1 - (k + 6 + q);
                    if (r >= 0 && (k + 6 + q) < nB + 1) GATHER_ROW(r)
                    asm volatile("cp.async.commit_group;" ::: "memory");
                }
                asm volatile("cp.async.wait_group 4;" ::: "memory");
            } else if (w < 4) {
                const int r1 = (len - 1 - k) & 7, r0 = (len - 2 - k) & 7;
                float2 n1 = ab[rb][j + 1];
                float2 n2 = ab[rb][j + 2];
                float eB1 = ringBl[r1] * LOG2E, eB0 = ringBl[r0] * LOG2E;
                float eA1 = ring[r1][4 + j] * LOG2E, eC1 = ring[r1][5 + j] * LOG2E,
                      eD1 = ring[r1][6 + j] * LOG2E;
                float eA0 = ring[r0][4 + j] * LOG2E, eC0 = ring[r0][5 + j] * LOG2E;
                acc += ex2f(eA1) + ex2f(eA0);
                // step k: own pair
                float nU = lse2(aU + eB1, aV + eA1);
                float nV = lse3(aV + eA1, n1.x + eB1, al1 ? (n1.y + eC1) : NEG2);
                nU = hasU ? nU : NEG2;  nV = hasV ? nV : NEG2;
                // step k: redundant pair j+1
                float nU1 = lse2(n1.x + eB1, n1.y + eC1);
                float nV1 = lse3(n1.y + eC1, n2.x + eB1, al2 ? (n2.y + eD1) : NEG2);
                nU1 = (j + 1 <= L) ? nU1 : NEG2;
                nV1 = (j + 1 <= L - 1) ? nV1 : NEG2;
                // step k+1: register-only
                float nU2 = lse2(nU + eB0, nV + eA0);
                float nV2 = lse3(nV + eA0, nU1 + eB0, al1 ? (nV1 + eC0) : NEG2);
                aU = hasU ? nU2 : NEG2;  aV = hasV ? nV2 : NEG2;
                ab[rb ^ 1][j] = make_float2(aU, aV);
            }
            rb ^= 1;
        }
        if (k < nB) {                    // leftover single step
            __syncthreads();
            if (w < 4) {
                const int r1 = (len - 1 - k) & 7;
                float2 n1 = ab[rb][j + 1];
                float eB1 = ringBl[r1] * LOG2E;
                float eA1 = ring[r1][4 + j] * LOG2E, eC1 = ring[r1][5 + j] * LOG2E;
                acc += ex2f(eA1);
                float nU = lse2(aU + eB1, aV + eA1);
                float nV = lse3(aV + eA1, n1.x + eB1, al1 ? (n1.y + eC1) : NEG2);
                aU = hasU ? nU : NEG2;  aV = hasV ? nV : NEG2;
            }
        }
    }
    if (w == 4) { asm volatile("cp.async.wait_group 0;" ::: "memory"); }

    // ---- publish mid-state + tps partials ----
    if (w < 4) {
        g_mid[b][dir][j][0] = aU;
        g_mid[b][dir][j][1] = aV;
        g_tps[b][dir][j]    = acc;
    }
    __threadfence();
    __syncthreads();
    if (tid == 0) sflag = atomicAdd(&g_done[b], 1u);
    __syncthreads();

    if (sflag == 1) {                    // second finisher: combine this sample
        float cU = NEG2, cV = NEG2, mj = NEG2;
        if (w < 4) {
            float a0 = __ldcg(&g_mid[b][0][j][0]), a1 = __ldcg(&g_mid[b][0][j][1]);
            float b0 = __ldcg(&g_mid[b][1][j][0]), b1 = __ldcg(&g_mid[b][1][j][1]);
            cU = a0 + b0;  cV = a1 + b1;
            mj = fmaxf(cU, cV);
            #pragma unroll
            for (int o = 16; o; o >>= 1) mj = fmaxf(mj, __shfl_xor_sync(0xFFFFFFFFu, mj, o));
            if (lane == 0) redm[w] = mj;
        }
        __syncthreads();
        float M = fmaxf(fmaxf(redm[0], redm[1]), fmaxf(redm[2], redm[3]));
        float sj = 0.0f, wgt = 0.0f;
        if (w < 4) {
            sj = ex2f(cU - M) + ex2f(cV - M);
            if (j < L) {
                float tps = __ldcg(&g_tps[b][0][j]) + __ldcg(&g_tps[b][1][j]);
                float om  = 1.0f - tps * (1.0f / (float)T);
                wgt = om * om;                       // GAMMA = 2
            }
            #pragma unroll
            for (int o = 16; o; o >>= 1) {
                sj  += __shfl_xor_sync(0xFFFFFFFFu, sj, o);
                wgt += __shfl_xor_sync(0xFFFFFFFFu, wgt, o);
            }
            if (lane == 0) { reds[w] = sj; redww[w] = wgt; }
        }
        __syncthreads();
        if (tid == 0) {
            float ss = reds[0] + reds[1] + reds[2] + reds[3];
            float ll = (M + lg2f(ss)) * LN2;
            g_loss[b] = (ll > -5e29f) ? -ll : 0.0f;   // zero_infinity
            g_wsum[b] = redww[0] + redww[1] + redww[2] + redww[3];
            g_done[b] = 0;                            // reset for graph replay
            finalize(out, B, L);
        }
    }
    #undef GATHER_ROW
}

extern "C" void kernel_launch(void* const* d_in, const int* in_sizes, int n_in,
                              void* d_out, int out_size)
{
    const float* lp      = (const float*)d_in[0];
    const int*   targets = (const int*)d_in[1];
    const int*   in_len  = (const int*)d_in[2];
    const int*   tg_len  = (const int*)d_in[3];

    int B = in_sizes[2];                 // 64
    int L = in_sizes[1] / B;             // 100
    int T = in_sizes[0] / (B * CFIX);    // 1000

    focal_ctc_kernel<<<2 * B, 160>>>(lp, targets, in_len, tg_len, (float*)d_out, T, B, L);
}